// round 15
// baseline (speedup 1.0000x reference)
#include <cuda_runtime.h>
#include <cuda_bf16.h>

// YOLOv3 loss, sm_103a — R10: R9 (separable IoU + box pruning) with
// APT=2 -> 576 blocks = ONE wave (R9's 1104 blocks @ 6 CTA/SM limit = 2 waves,
// the 2nd ~20% full), and ballot-gated reductions (warps with no positive
// anchor — the common case — skip the 45-shfl reduce chain).

#define NUM_CLASSES 80
#define NA 3
#define MAXB 64
#define MAXK 32
#define GMAX 96          // max grid dim for smem tables (G=76 here)
#define NRMAX 12         // rows a 512-anchor chunk can span (<=8 for G=76)
#define TPB 256
#define APT 2            // anchors per thread (chunk = TPB*APT = 512)

__device__ float        g_cls_sum[MAXB];   // zero-init at load; self-reset
__device__ float        g_reg_sum[MAXB];
__device__ float        g_npos[MAXB];
__device__ unsigned int g_done;

__device__ __forceinline__ float sigmoidf_fast(float x) {
    return 1.0f / (1.0f + __expf(-x));
}

// Cold path (~0.3% of anchors): exact argmax over the compacted survivor set
// + loss accumulation. Pruned boxes provably cannot win for a positive anchor
// (feasibility-pruned have IoU<0.5 <= winner's; y-pruned have inter=0 here).
__device__ __noinline__ void anchor_loss(
    int a, int G, float stride, float hw, float hh, float aw, float ah,
    const float4* s_box, const float4* s_aux, const float* s_cl,
    const float* s_thr, int K, const float* __restrict__ row,
    float& clsc, float& regc)
{
    const int   r  = a / G, c = a - (a / G) * G;
    const float ax = ((float)c + 0.5f) * stride;
    const float ay = ((float)r + 0.5f) * stride;
    const float ax1 = ax - hw, ay1 = ay - hh;
    const float ax2 = ax + hw, ay2 = ay + hh;

    // (inter,union) cross-mult argmax; strict '>' keeps first max (jnp.argmax).
    float bI = -1.f, bU = 1.f;
    int   bk = 0;
    for (int k = 0; k < K; k++) {
        float4 cb = s_box[k];
        float iw = fmaxf(fminf(ax2, cb.z) - fmaxf(ax1, cb.x), 0.f);
        float ih = fmaxf(fminf(ay2, cb.w) - fmaxf(ay1, cb.y), 0.f);
        float inter = iw * ih;
        float uni   = s_thr[k] - inter;              // areaA + am - inter
        if (inter * bU > bI * uni) { bI = inter; bU = uni; bk = k; }
    }

    const float4 bx = s_aux[bk];                     // cx,cy,w,h

    // regression: sum of squared errors (both /denom deferred to finalize)
    float r0 = row[0], r1 = row[1], r2 = row[2], r3 = row[3], r4 = row[4];
    float stx = sigmoidf_fast(bx.x - ax);
    float sty = sigmoidf_fast(bx.y - ay);
    float tw  = __logf(fmaxf(bx.z, 1.f) / aw);
    float th  = __logf(fmaxf(bx.w, 1.f) / ah);
    float d0 = sigmoidf_fast(r0) - stx;
    float d1 = sigmoidf_fast(r1) - sty;
    float d2 = r2 - tw;
    float d3 = r3 - th;
    float d4 = r4 - 1.0f;
    regc += d0*d0 + d1*d1 + d2*d2 + d3*d3 + d4*d4;

    // one-hot BCE collapsed: -( log p_t - log(1-p_t) + Σc log(1-p_c) )
    float acc = 0.f;
    #pragma unroll 8
    for (int cc = 0; cc < NUM_CLASSES; cc++)
        acc += __logf(1.0f - row[5 + cc]);
    int tcl = (int)s_cl[bk];
    float pt = row[5 + tcl];
    clsc += -(__logf(pt) - __logf(1.0f - pt) + acc);
}

__global__ void __launch_bounds__(TPB)
yolo_loss_sep(const float* __restrict__ pred,
              const float* __restrict__ ann,
              const float* __restrict__ anchors,
              float* __restrict__ out,
              int A, int G2, int G, int M, int B) {
    __shared__ float4 s_box[MAXK];          // bx1,by1,bx2,by2 (survivors)
    __shared__ float4 s_aux[MAXK];          // cx,cy,w,h
    __shared__ float  s_cl[MAXK];
    __shared__ float  s_thr[MAXK];          // areaA + am
    __shared__ float  s_iw[MAXK * GMAX];    // clamped overlap width per col
    __shared__ float  s_ih[MAXK * NRMAX];   // clamped overlap height per row
    __shared__ int    s_cnt;
    __shared__ int    s_last;

    const int tid = threadIdx.x;
    const int bt  = blockIdx.y;             // (image, type)
    const int b   = bt / NA;
    const int t   = bt - b * NA;

    const float stride = 2.0f * __ldg(&anchors[0]);       // cx(col0)=0.5*stride
    const float aw = __ldg(&anchors[(size_t)t * G2 * 4 + 2]);
    const float ah = __ldg(&anchors[(size_t)t * G2 * 4 + 3]);
    const float hw = 0.5f * aw, hh = 0.5f * ah;
    const float areaA = aw * ah;

    // this block's anchor range within the (b,t) plane, and its row band
    const int a0 = blockIdx.x * (TPB * APT);
    const int a1 = min(a0 + TPB * APT - 1, G2 - 1);
    const int r0 = a0 / G;
    const int r1 = a1 / G;
    const int nrows = r1 - r0 + 1;          // <= 8 for G=76

    // ---- warp 0: prune + compact boxes ----
    if (tid < 32) {
        bool  keep = false;
        float x = 0.f, y = 0.f, w = 0.f, h = 0.f, cl = -1.f, am = 0.f;
        if (tid < M) {
            const float* bm = ann + (size_t)(b * M + tid) * 5;
            x = bm[0]; y = bm[1]; w = bm[2]; h = bm[3]; cl = bm[4];
            if (cl != -1.0f) {
                am = w * h;
                // (a) type feasibility: inter <= min(aw,w)*min(ah,h)
                bool feas = 3.0f * fminf(aw, w) * fminf(ah, h) >= areaA + am;
                // (b) y-band overlap with this block's rows (conservative)
                float ay_min = ((float)r0 + 0.5f) * stride;
                float ay_max = ((float)r1 + 0.5f) * stride;
                bool yov = (ay_min <= (y + h) + hh) && (ay_max >= y - hh);
                keep = feas && yov;
            }
        }
        unsigned mask = __ballot_sync(0xffffffffu, keep);
        if (keep) {
            int k = __popc(mask & ((1u << tid) - 1u));
            s_box[k] = make_float4(x, y, x + w, y + h);
            s_aux[k] = make_float4(x + 0.5f * w, y + 0.5f * h, w, h);
            s_cl[k]  = cl;
            s_thr[k] = areaA + am;
        }
        if (tid == 0) s_cnt = __popc(mask);
    }
    __syncthreads();

    const int K = s_cnt;

    // ---- separable overlap tables (K*G + K*nrows entries total) ----
    for (int i = tid; i < K * G; i += TPB) {
        int k = i / G, col = i - k * G;
        float ax = ((float)col + 0.5f) * stride;     // bitwise == anchors array
        float4 c = s_box[k];
        float iw = fminf(ax + hw, c.z) - fmaxf(ax - hw, c.x);
        s_iw[k * GMAX + col] = fmaxf(iw, 0.f);
    }
    for (int i = tid; i < K * nrows; i += TPB) {
        int k = i / nrows, ri = i - k * nrows;
        float ay = ((float)(r0 + ri) + 0.5f) * stride;
        float4 c = s_box[k];
        float ih = fminf(ay + hh, c.w) - fmaxf(ay - hh, c.y);
        s_ih[k * NRMAX + ri] = fmaxf(ih, 0.f);
    }
    __syncthreads();

    float clsc = 0.f, regc = 0.f, posc = 0.f;

    // ---- HOT: 2 anchors/thread, K iters of 2 LDS + FMUL + compare each ----
    #pragma unroll
    for (int j = 0; j < APT; j++) {
        const int a = a0 + j * TPB + tid;
        if (a >= G2) break;
        const int r  = a / G;
        const int c  = a - r * G;
        const int ri = r - r0;

        bool hit = false;
        for (int k = 0; k < K; k++) {
            float inter = s_iw[k * GMAX + c] * s_ih[k * NRMAX + ri];
            hit |= (3.0f * inter >= s_thr[k]);   // IoU>=0.5, exact, div-free
        }
        if (hit) {
            posc += 1.f;
            const float* row = pred +
                (size_t)((b * NA + t) * G2 + a) * (NUM_CLASSES + 5);
            anchor_loss(a, G, stride, hw, hh, aw, ah,
                        s_box, s_aux, s_cl, s_thr, K, row, clsc, regc);
        }
    }

    // ---- ballot-gated warp reduce (common case: no positives -> skip) ----
    const unsigned full = 0xffffffffu;
    if (__ballot_sync(full, posc > 0.f)) {
        #pragma unroll
        for (int off = 16; off > 0; off >>= 1) {
            clsc += __shfl_down_sync(full, clsc, off);
            regc += __shfl_down_sync(full, regc, off);
            posc += __shfl_down_sync(full, posc, off);
        }
        if ((tid & 31) == 0) {
            atomicAdd(&g_cls_sum[b], clsc);
            atomicAdd(&g_reg_sum[b], regc);
            atomicAdd(&g_npos[b],    posc);
        }
    }

    // ---- last-block finalize ----
    __syncthreads();
    if (tid == 0) {
        __threadfence();
        unsigned total = gridDim.x * gridDim.y;
        unsigned old = atomicAdd(&g_done, 1u);
        s_last = (old == total - 1u);
    }
    __syncthreads();

    if (s_last && tid < 32) {
        __threadfence();
        float cl = 0.f, rg = 0.f;
        if (tid < B) {
            float n = g_npos[tid];
            float denom = fmaxf(n, 1.f);
            cl = g_cls_sum[tid] / denom;
            rg = (n > 0.f) ? g_reg_sum[tid] / (denom * denom) : 0.f;
            g_cls_sum[tid] = 0.f;
            g_reg_sum[tid] = 0.f;
            g_npos[tid]    = 0.f;
        }
        #pragma unroll
        for (int off = 16; off > 0; off >>= 1) {
            cl += __shfl_down_sync(full, cl, off);
            rg += __shfl_down_sync(full, rg, off);
        }
        if (tid == 0) {
            out[0] = cl / (float)B;
            out[1] = rg / (float)B;
            g_done = 0u;
        }
    }
}

extern "C" void kernel_launch(void* const* d_in, const int* in_sizes, int n_in,
                              void* d_out, int out_size) {
    const float* pred    = (const float*)d_in[0];  // (B, NA*G2, 5+C) f32
    const float* ann     = (const float*)d_in[1];  // (B, M, 5) f32
    const float* anchors = (const float*)d_in[2];  // (NA, G, G, 4) f32
    float* out = (float*)d_out;

    const int A  = in_sizes[2] / 4;
    const int G2 = A / NA;
    const int G  = (int)(sqrtf((float)G2) + 0.5f);
    const int B  = in_sizes[0] / (A * (NUM_CLASSES + 5));
    const int M  = in_sizes[1] / (B * 5);

    dim3 grid((G2 + TPB * APT - 1) / (TPB * APT), B * NA);  // 12 x 48 = 576
    yolo_loss_sep<<<grid, TPB>>>(pred, ann, anchors, out, A, G2, G, M, B);
}

// round 17
// speedup vs baseline: 1.0290x; 1.0290x over previous
#include <cuda_runtime.h>
#include <cuda_bf16.h>

// YOLOv3 loss, sm_103a — R11: R9 (separable IoU + per-block box pruning,
// APT=1, 1104 blocks) + __launch_bounds__(256,8) so all 1104 CTAs fit in ONE
// wave (148*8=1184; R9's regs=40 -> 6 CTA/SM -> 888-cap wave1 + 20%-full
// wave2 tail), + ballot-gated reductions, + __noinline__ cold path to keep
// hot-path regs under the 32-reg cap.

#define NUM_CLASSES 80
#define NA 3
#define MAXB 64
#define MAXK 32
#define GMAX 96          // max grid dim for smem tables (G=76 here)
#define NRMAX 8          // rows a 256-anchor chunk can span (<=5 for G=76)
#define TPB 256

__device__ float        g_cls_sum[MAXB];   // zero-init at load; self-reset
__device__ float        g_reg_sum[MAXB];
__device__ float        g_npos[MAXB];
__device__ unsigned int g_done;

__device__ __forceinline__ float sigmoidf_fast(float x) {
    return 1.0f / (1.0f + __expf(-x));
}

// Cold path (~0.3% of anchors): exact argmax over the compacted survivor set
// + loss accumulation. Pruned boxes provably cannot win for a positive anchor
// (feasibility-pruned have IoU<0.5 <= winner's; y-pruned have inter=0 here).
__device__ __noinline__ void anchor_loss(
    float ax, float ay, float hw, float hh, float aw, float ah,
    const float4* s_box, const float4* s_aux, const float* s_cl,
    const float* s_thr, int K, const float* __restrict__ row,
    float& clsc, float& regc)
{
    const float ax1 = ax - hw, ay1 = ay - hh;
    const float ax2 = ax + hw, ay2 = ay + hh;

    // (inter,union) cross-mult argmax; strict '>' keeps first max (jnp.argmax).
    float bI = -1.f, bU = 1.f;
    int   bk = 0;
    for (int k = 0; k < K; k++) {
        float4 cb = s_box[k];
        float iw = fmaxf(fminf(ax2, cb.z) - fmaxf(ax1, cb.x), 0.f);
        float ih = fmaxf(fminf(ay2, cb.w) - fmaxf(ay1, cb.y), 0.f);
        float inter = iw * ih;
        float uni   = s_thr[k] - inter;              // areaA + am - inter
        if (inter * bU > bI * uni) { bI = inter; bU = uni; bk = k; }
    }

    const float4 bx = s_aux[bk];                     // cx,cy,w,h

    // regression: sum of squared errors (both /denom deferred to finalize)
    float r0 = row[0], r1 = row[1], r2 = row[2], r3 = row[3], r4 = row[4];
    float stx = sigmoidf_fast(bx.x - ax);
    float sty = sigmoidf_fast(bx.y - ay);
    float tw  = __logf(fmaxf(bx.z, 1.f) / aw);
    float th  = __logf(fmaxf(bx.w, 1.f) / ah);
    float d0 = sigmoidf_fast(r0) - stx;
    float d1 = sigmoidf_fast(r1) - sty;
    float d2 = r2 - tw;
    float d3 = r3 - th;
    float d4 = r4 - 1.0f;
    regc += d0*d0 + d1*d1 + d2*d2 + d3*d3 + d4*d4;

    // one-hot BCE collapsed: -( log p_t - log(1-p_t) + Σc log(1-p_c) )
    float acc = 0.f;
    #pragma unroll 8
    for (int cc = 0; cc < NUM_CLASSES; cc++)
        acc += __logf(1.0f - row[5 + cc]);
    int tcl = (int)s_cl[bk];
    float pt = row[5 + tcl];
    clsc += -(__logf(pt) - __logf(1.0f - pt) + acc);
}

__global__ void __launch_bounds__(TPB, 8)
yolo_loss_sep(const float* __restrict__ pred,
              const float* __restrict__ ann,
              const float* __restrict__ anchors,
              float* __restrict__ out,
              int A, int G2, int G, int M, int B) {
    __shared__ float4 s_box[MAXK];          // bx1,by1,bx2,by2 (survivors)
    __shared__ float4 s_aux[MAXK];          // cx,cy,w,h
    __shared__ float  s_cl[MAXK];
    __shared__ float  s_thr[MAXK];          // areaA + am
    __shared__ float  s_iw[MAXK * GMAX];    // clamped overlap width per col
    __shared__ float  s_ih[MAXK * NRMAX];   // clamped overlap height per row
    __shared__ int    s_cnt;
    __shared__ int    s_last;

    const int tid = threadIdx.x;
    const int bt  = blockIdx.y;             // (image, type)
    const int b   = bt / NA;
    const int t   = bt - b * NA;

    const float stride = 2.0f * __ldg(&anchors[0]);       // cx(col0)=0.5*stride
    const float aw = __ldg(&anchors[(size_t)t * G2 * 4 + 2]);
    const float ah = __ldg(&anchors[(size_t)t * G2 * 4 + 3]);
    const float hw = 0.5f * aw, hh = 0.5f * ah;
    const float areaA = aw * ah;

    // this block's anchor range within the (b,t) plane, and its row band
    const int a0 = blockIdx.x * TPB;
    const int a1 = min(a0 + TPB - 1, G2 - 1);
    const int r0 = a0 / G;
    const int r1 = a1 / G;
    const int nrows = r1 - r0 + 1;          // <= 5 for G=76

    // ---- warp 0: prune + compact boxes ----
    if (tid < 32) {
        bool  keep = false;
        float x = 0.f, y = 0.f, w = 0.f, h = 0.f, cl = -1.f, am = 0.f;
        if (tid < M) {
            const float* bm = ann + (size_t)(b * M + tid) * 5;
            x = bm[0]; y = bm[1]; w = bm[2]; h = bm[3]; cl = bm[4];
            if (cl != -1.0f) {
                am = w * h;
                // (a) type feasibility: inter <= min(aw,w)*min(ah,h)
                bool feas = 3.0f * fminf(aw, w) * fminf(ah, h) >= areaA + am;
                // (b) y-band overlap with this block's rows (conservative)
                float ay_min = ((float)r0 + 0.5f) * stride;
                float ay_max = ((float)r1 + 0.5f) * stride;
                bool yov = (ay_min <= (y + h) + hh) && (ay_max >= y - hh);
                keep = feas && yov;
            }
        }
        unsigned mask = __ballot_sync(0xffffffffu, keep);
        if (keep) {
            int k = __popc(mask & ((1u << tid) - 1u));
            s_box[k] = make_float4(x, y, x + w, y + h);
            s_aux[k] = make_float4(x + 0.5f * w, y + 0.5f * h, w, h);
            s_cl[k]  = cl;
            s_thr[k] = areaA + am;
        }
        if (tid == 0) s_cnt = __popc(mask);
    }
    __syncthreads();

    const int K = s_cnt;

    // ---- separable overlap tables (K*G + K*nrows entries total) ----
    for (int i = tid; i < K * G; i += TPB) {
        int k = i / G, col = i - k * G;
        float ax = ((float)col + 0.5f) * stride;     // bitwise == anchors array
        float4 c = s_box[k];
        float iw = fminf(ax + hw, c.z) - fmaxf(ax - hw, c.x);
        s_iw[k * GMAX + col] = fmaxf(iw, 0.f);
    }
    for (int i = tid; i < K * nrows; i += TPB) {
        int k = i / nrows, ri = i - k * nrows;
        float ay = ((float)(r0 + ri) + 0.5f) * stride;
        float4 c = s_box[k];
        float ih = fminf(ay + hh, c.w) - fmaxf(ay - hh, c.y);
        s_ih[k * NRMAX + ri] = fmaxf(ih, 0.f);
    }
    __syncthreads();

    const int a = a0 + tid;                 // anchor index within (b,t) plane
    float clsc = 0.f, regc = 0.f, posc = 0.f;

    if (a < G2) {
        const int r  = a / G;
        const int c  = a - r * G;
        const int ri = r - r0;

        // ---- HOT: K iters of 2 LDS + FMUL + compare ----
        bool hit = false;
        for (int k = 0; k < K; k++) {
            float inter = s_iw[k * GMAX + c] * s_ih[k * NRMAX + ri];
            hit |= (3.0f * inter >= s_thr[k]);   // IoU>=0.5, exact, div-free
        }

        if (hit) {
            posc = 1.f;
            const float ax = ((float)c + 0.5f) * stride;
            const float ay = ((float)r + 0.5f) * stride;
            const float* row = pred +
                (size_t)((b * NA + t) * G2 + a) * (NUM_CLASSES + 5);
            anchor_loss(ax, ay, hw, hh, aw, ah,
                        s_box, s_aux, s_cl, s_thr, K, row, clsc, regc);
        }
    }

    // ---- ballot-gated warp reduce (common case: no positives -> skip) ----
    const unsigned full = 0xffffffffu;
    if (__ballot_sync(full, posc > 0.f)) {
        #pragma unroll
        for (int off = 16; off > 0; off >>= 1) {
            clsc += __shfl_down_sync(full, clsc, off);
            regc += __shfl_down_sync(full, regc, off);
            posc += __shfl_down_sync(full, posc, off);
        }
        if ((tid & 31) == 0) {
            atomicAdd(&g_cls_sum[b], clsc);
            atomicAdd(&g_reg_sum[b], regc);
            atomicAdd(&g_npos[b],    posc);
        }
    }

    // ---- last-block finalize ----
    __syncthreads();
    if (tid == 0) {
        __threadfence();
        unsigned total = gridDim.x * gridDim.y;
        unsigned old = atomicAdd(&g_done, 1u);
        s_last = (old == total - 1u);
    }
    __syncthreads();

    if (s_last && tid < 32) {
        __threadfence();
        float cl = 0.f, rg = 0.f;
        if (tid < B) {
            float n = g_npos[tid];
            float denom = fmaxf(n, 1.f);
            cl = g_cls_sum[tid] / denom;
            rg = (n > 0.f) ? g_reg_sum[tid] / (denom * denom) : 0.f;
            g_cls_sum[tid] = 0.f;
            g_reg_sum[tid] = 0.f;
            g_npos[tid]    = 0.f;
        }
        #pragma unroll
        for (int off = 16; off > 0; off >>= 1) {
            cl += __shfl_down_sync(full, cl, off);
            rg += __shfl_down_sync(full, rg, off);
        }
        if (tid == 0) {
            out[0] = cl / (float)B;
            out[1] = rg / (float)B;
            g_done = 0u;
        }
    }
}

extern "C" void kernel_launch(void* const* d_in, const int* in_sizes, int n_in,
                              void* d_out, int out_size) {
    const float* pred    = (const float*)d_in[0];  // (B, NA*G2, 5+C) f32
    const float* ann     = (const float*)d_in[1];  // (B, M, 5) f32
    const float* anchors = (const float*)d_in[2];  // (NA, G, G, 4) f32
    float* out = (float*)d_out;

    const int A  = in_sizes[2] / 4;
    const int G2 = A / NA;
    const int G  = (int)(sqrtf((float)G2) + 0.5f);
    const int B  = in_sizes[0] / (A * (NUM_CLASSES + 5));
    const int M  = in_sizes[1] / (B * 5);

    dim3 grid((G2 + TPB - 1) / TPB, B * NA);   // 23 x 48 = 1104 blocks, 1 wave
    yolo_loss_sep<<<grid, TPB>>>(pred, ann, anchors, out, A, G2, G, M, B);
}